// round 15
// baseline (speedup 1.0000x reference)
#include <cuda_runtime.h>
#include <cuda_bf16.h>
#include <cuda_fp16.h>
#include <math_constants.h>
#include <cstdint>

#define HW 9216            // 96*96
#define CK 392             // 256 + 136
#define NF (256 * HW)
#define KSEG 416           // full-K hi segment (13 chunks of 32)
#define KLM 160            // landmark cross segment (136 padded to 160)
#define KBIG 736           // [Ah_full | Ah_lm | Al_lm] x [Bh_full | Bl_lm | Bh_lm]
#define NCHKS 23           // KBIG / 32
#define NBLK 144           // row blocks of 64 (per-warp colstat partials)
#define ASTG 8192          // A stage bytes: 128 rows x 64B
#define BSTG 8192          // B stage bytes: 128 rows x 64B
#define GEMM_DSMEM (4 * (ASTG + BSTG))   // 64 KB, 4-stage ring -> 2 CTAs/SM

// ===================== static device scratch =====================
__device__ __align__(16) __nv_bfloat16 g_Abig[(size_t)HW * KBIG]; // (9216,736) K-major
__device__ __align__(16) __nv_bfloat16 g_Bbig[(size_t)HW * KBIG]; // transposed (n,k) K-major
__device__ __align__(16) __half g_E[(size_t)HW * HW];             // 170 MB exp(A - blkmax)
__device__ float g_pm[(size_t)NBLK * HW];
__device__ float g_ps[(size_t)NBLK * HW];
__device__ __align__(16) float2 g_wcomb[(size_t)NBLK * HW];       // (wb, wg) per (blk, col)
__device__ float g_beta[HW], g_gama[HW], g_M[HW];
__device__ float g_bhat[HW], g_ghat[HW];

// ===================== PTX helpers (non-'a' features only) =====================
__device__ __forceinline__ uint32_t smem_u32(const void* p) {
    uint32_t a;
    asm("{ .reg .u64 t; cvta.to.shared.u64 t, %1; cvt.u32.u64 %0, t; }" : "=r"(a) : "l"(p));
    return a;
}
__device__ __forceinline__ void cp16(uint32_t saddr, const void* g) {
    asm volatile("cp.async.cg.shared.global [%0], [%1], 16;" :: "r"(saddr), "l"(g));
}
#define CP_COMMIT() asm volatile("cp.async.commit_group;" ::: "memory")
#define CP_WAIT(n)  asm volatile("cp.async.wait_group %0;" :: "n"(n) : "memory")
#define LDSM_X4(r0, r1, r2, r3, addr) \
    asm volatile("ldmatrix.sync.aligned.m8n8.x4.shared.b16 {%0,%1,%2,%3}, [%4];" \
        : "=r"(r0), "=r"(r1), "=r"(r2), "=r"(r3) : "r"(addr))
#define MMA16816(d, a, b) \
    asm volatile("mma.sync.aligned.m16n8k16.row.col.f32.bf16.bf16.f32 " \
        "{%0,%1,%2,%3}, {%4,%5,%6,%7}, {%8,%9}, {%0,%1,%2,%3};" \
        : "+f"((d)[0]), "+f"((d)[1]), "+f"((d)[2]), "+f"((d)[3]) \
        : "r"((a)[0]), "r"((a)[1]), "r"((a)[2]), "r"((a)[3]), "r"((b)[0]), "r"((b)[1]))

// smem tile layout: [rows][32 bf16] = 64B rows; 16B-chunk swizzle c ^= (r>>1)&3
__device__ __forceinline__ uint32_t swz(int r, int c) {
    return (uint32_t)(r * 64 + ((c ^ ((r >> 1) & 3)) << 4));
}

// 1a) A': seg0 = hi(full k, padded), seg1 = hi(landmark), seg2 = lo(landmark).
__global__ void prep_src_bf16(const float* __restrict__ fs, const float* __restrict__ ls) {
    int t = blockIdx.x * blockDim.x + threadIdx.x;
    if (t >= HW * KBIG) return;
    int m = t / KBIG, kp = t - m * KBIG;
    int k;
    bool lo = false;
    if (kp < KSEG)            k = kp;                       // hi, full K
    else if (kp < KSEG + KLM) k = 256 + (kp - KSEG);        // hi, landmark
    else { k = 256 + (kp - KSEG - KLM); lo = true; }        // lo, landmark
    float x = 0.0f;
    if (k < CK) {
        int s = m * CK + k;
        x = (s < NF) ? 0.01f * fs[s] : ls[s - NF];
    }
    __nv_bfloat16 h = __float2bfloat16(x);
    g_Abig[t] = lo ? __float2bfloat16(x - __bfloat162float(h)) : h;
}

// 1b) B' transposed: seg0 = hi(full), seg1 = lo(landmark), seg2 = hi(landmark).
__global__ void prep_ref_bf16(const float* __restrict__ fr, const float* __restrict__ lr) {
    __shared__ float tile[32][33];
    int k0 = blockIdx.y * 32, n0 = blockIdx.x * 32;
    int tx = threadIdx.x, ty = threadIdx.y;   // (32, 8)
#pragma unroll
    for (int i = 0; i < 32; i += 8) {
        int k = k0 + ty + i, n = n0 + tx;
        float x = 0.0f;
        if (k < CK) x = (k < 256) ? 0.01f * fr[k * HW + n] : lr[(k - 256) * HW + n];
        tile[ty + i][tx] = x;
    }
    __syncthreads();
#pragma unroll
    for (int i = 0; i < 32; i += 8) {
        int n = n0 + ty + i, k = k0 + tx;       // k in [0, 416)
        float x = tile[tx][ty + i];
        __nv_bfloat16 h = __float2bfloat16(x);
        size_t o = (size_t)n * KBIG;
        g_Bbig[o + k] = h;                       // seg0: hi full
        if (k >= 256) {                          // landmark (incl. zero pad k>=392)
            int j = k - 256;                     // [0, 160)
            g_Bbig[o + KSEG + j] = __float2bfloat16(x - __bfloat162float(h));  // seg1: lo
            g_Bbig[o + KSEG + KLM + j] = h;                                    // seg2: hi
        }
    }
}

// 2) 1x1 convs (256->1) + mask equality vector.
__global__ void prep_betagama(const float* __restrict__ fr,
                              const int* __restrict__ ms, const int* __restrict__ mr,
                              const float* __restrict__ w1, const float* __restrict__ b1,
                              const float* __restrict__ w2, const float* __restrict__ b2) {
    int p = blockIdx.x * blockDim.x + threadIdx.x;
    if (p >= HW) return;
    float b = b1[0], g = b2[0];
#pragma unroll 8
    for (int c = 0; c < 256; c++) {
        float v = fr[c * HW + p];
        b = fmaf(v, w1[c], b);
        g = fmaf(v, w2[c], g);
    }
    g_beta[p] = b;
    g_gama[p] = g;
    g_M[p] = (ms[p] == mr[p]) ? 1.0f : 0.0f;
}

// 3) bf16 HMMA GEMM, epilogue stores e = exp(acc - per-64-row-block colmax) as fp16
//    plus (max, sumexp) partials per (64-row warp block, column). No logit array.
//    128x128 CTA tile, 128 threads: 4 warps of 64x64 (2m x 2n), BK=32,
//    4-stage cp.async ring (64 KB -> 2 CTAs/SM), one barrier per chunk.
__global__ void __launch_bounds__(128, 2) gemm_hmma_kernel() {
    extern __shared__ __align__(128) char smem_raw[];
    const uint32_t sAu = smem_u32(smem_raw);            // 4 stages x 8192 B
    const uint32_t sBu = sAu + 4 * ASTG;                // 4 stages x 8192 B
    const int tid = threadIdx.x;
    const int wid = tid >> 5, lane = tid & 31;
    const size_t m0 = (size_t)blockIdx.y * 128;
    const size_t n0 = (size_t)blockIdx.x * 128;
    const int mw = (wid & 1) * 64;   // warp m offset in tile
    const int nw = (wid >> 1) * 64;  // warp n offset in tile

    // per-thread load slots: each stage = 512 16B-chunks -> 4 per thread (A and B)
    const int lc0 = tid & 3;
    uint32_t saS[4];
    const __nv_bfloat16 *gA[4], *gB[4];
#pragma unroll
    for (int j = 0; j < 4; ++j) {
        int r = (tid + j * 128) >> 2;
        saS[j] = swz(r, lc0);
        gA[j] = g_Abig + (m0 + r) * KBIG + lc0 * 8;
        gB[j] = g_Bbig + (n0 + r) * KBIG + lc0 * 8;
    }

    float acc[4][8][4];
#pragma unroll
    for (int i = 0; i < 4; i++)
#pragma unroll
        for (int j = 0; j < 8; j++)
#pragma unroll
            for (int q = 0; q < 4; q++) acc[i][j][q] = 0.0f;

    // ldmatrix lane address components (swizzled)
    const int a_r = (lane & 7) + ((lane >> 3) & 1) * 8;
    const int a_c = lane >> 4;
    const int b_r = (lane & 7) + (lane >> 4) * 8;
    const int b_c = (lane >> 3) & 1;

    // prologue: prefetch chunks 0..2 into ring slots 0..2
#pragma unroll
    for (int p = 0; p < 3; ++p) {
        const uint32_t oa = (uint32_t)p * ASTG, ob = (uint32_t)p * BSTG;
        const size_t kofs = (size_t)p * 32;
#pragma unroll
        for (int j = 0; j < 4; ++j) {
            cp16(sAu + oa + saS[j], gA[j] + kofs);
            cp16(sBu + ob + saS[j], gB[j] + kofs);
        }
        CP_COMMIT();
    }

    for (int ch = 0; ch < NCHKS; ++ch) {
        if (ch < NCHKS - 2)      { CP_WAIT(2); }
        else if (ch == NCHKS - 2){ CP_WAIT(1); }
        else                     { CP_WAIT(0); }
        __syncthreads();
        if (ch + 3 < NCHKS) {    // refill ring slot (ch+3)&3 == (ch-1)&3 (free after barrier)
            const uint32_t oa = (uint32_t)((ch + 3) & 3) * ASTG;
            const uint32_t ob = (uint32_t)((ch + 3) & 3) * BSTG;
            const size_t kofs = (size_t)(ch + 3) * 32;
#pragma unroll
            for (int j = 0; j < 4; ++j) {
                cp16(sAu + oa + saS[j], gA[j] + kofs);
                cp16(sBu + ob + saS[j], gB[j] + kofs);
            }
            CP_COMMIT();
        }

        const uint32_t ab = sAu + (uint32_t)(ch & 3) * ASTG;
        const uint32_t bb = sBu + (uint32_t)(ch & 3) * BSTG;
#pragma unroll
        for (int ks = 0; ks < 2; ++ks) {
            uint32_t afr[4][4], bfr[8][2];
#pragma unroll
            for (int mt = 0; mt < 4; ++mt) {
                int r = mw + mt * 16 + a_r;
                LDSM_X4(afr[mt][0], afr[mt][1], afr[mt][2], afr[mt][3],
                        ab + swz(r, 2 * ks + a_c));
            }
#pragma unroll
            for (int np = 0; np < 4; ++np) {
                int r = nw + np * 16 + b_r;
                LDSM_X4(bfr[np * 2][0], bfr[np * 2][1], bfr[np * 2 + 1][0], bfr[np * 2 + 1][1],
                        bb + swz(r, 2 * ks + b_c));
            }
#pragma unroll
            for (int mt = 0; mt < 4; ++mt)
#pragma unroll
                for (int nt = 0; nt < 8; ++nt)
                    MMA16816(acc[mt][nt], afr[mt], bfr[nt]);
        }
    }

    // ---- epilogue: per-warp (64-row) column stats + fp16 e store ----
    // Warp's 64 rows = one stats block: blkrow = blockIdx.y*2 + (wid&1).
    // Butterfly offsets 4/8/16 reduce the 8 lane row-groups preserving lane&3 (column).
    const size_t mbase = m0 + mw + (lane >> 2);
    const size_t nbase = n0 + nw + 2 * (lane & 3);
    const size_t blkrow = (size_t)blockIdx.y * 2 + (wid & 1);
#pragma unroll
    for (int nt = 0; nt < 8; ++nt) {
        float ev[4][4];
#pragma unroll
        for (int p = 0; p < 2; ++p) {
            float mx = -CUDART_INF_F;
#pragma unroll
            for (int mt = 0; mt < 4; ++mt)
                mx = fmaxf(mx, fmaxf(acc[mt][nt][p], acc[mt][nt][p + 2]));
#pragma unroll
            for (int o = 4; o < 32; o <<= 1)
                mx = fmaxf(mx, __shfl_xor_sync(0xFFFFFFFFu, mx, o));
            float se = 0.0f;
#pragma unroll
            for (int mt = 0; mt < 4; ++mt) {
                ev[mt][p]     = __expf(acc[mt][nt][p]     - mx);
                ev[mt][p + 2] = __expf(acc[mt][nt][p + 2] - mx);
                se += ev[mt][p] + ev[mt][p + 2];
            }
#pragma unroll
            for (int o = 4; o < 32; o <<= 1)
                se += __shfl_xor_sync(0xFFFFFFFFu, se, o);
            if (lane < 4) {
                size_t col = n0 + (size_t)(wid >> 1) * 64 + nt * 8 + 2 * lane + p;
                g_pm[blkrow * HW + col] = mx;
                g_ps[blkrow * HW + col] = se;
            }
        }
#pragma unroll
        for (int mt = 0; mt < 4; ++mt) {
            size_t r = mbase + mt * 16, c = nbase + nt * 8;
            *(__half2*)&g_E[r * HW + c]       = __floats2half2_rn(ev[mt][0], ev[mt][1]);
            *(__half2*)&g_E[(r + 8) * HW + c] = __floats2half2_rn(ev[mt][2], ev[mt][3]);
        }
    }
}

// 5) Merge 144 per-block partials; emit per-(block,col) combined weights:
//    wcomb[blk][j] = (M[j]*beta[j]/S[j]) * exp(pm[blk][j] - m_global[j])  (and gama).
__global__ void mergestats_kernel() {
    int j = blockIdx.x * blockDim.x + threadIdx.x;
    float m = -CUDART_INF_F;
    for (int c = 0; c < NBLK; c++) m = fmaxf(m, g_pm[(size_t)c * HW + j]);
    float s = 0.0f;
    for (int c = 0; c < NBLK; c++)
        s += g_ps[(size_t)c * HW + j] * __expf(g_pm[(size_t)c * HW + j] - m);
    float wb = g_M[j] * g_beta[j] / s;
    float wg = g_M[j] * g_gama[j] / s;
    for (int c = 0; c < NBLK; c++) {
        float corr = __expf(g_pm[(size_t)c * HW + j] - m);
        g_wcomb[(size_t)c * HW + j] = make_float2(wb * corr, wg * corr);
    }
}

// 6) rowsum: beta_hat[i] = sum_j e[i,j] * wcomb[blk(i)][j].x (gama: .y).
//    CTA = 32 rows (4 warps x 8 rows); wcomb strip staged in smem; 4 rows per
//    inner iteration share each smem weight load (2B smem/element).
__global__ void __launch_bounds__(128) rowsum_kernel() {
    __shared__ __align__(16) float2 sw[1024];
    const int tid = threadIdx.x, wid = tid >> 5, lane = tid & 31;
    const int row0 = blockIdx.x * 32;
    const size_t blk = (size_t)(row0 >> 6);
    const int wrow0 = row0 + wid * 8;
    float accB[8], accG[8];
#pragma unroll
    for (int r = 0; r < 8; ++r) { accB[r] = 0.0f; accG[r] = 0.0f; }

    for (int strip = 0; strip < HW; strip += 1024) {
        __syncthreads();
        const float2* wsrc = g_wcomb + blk * HW + strip;
        for (int t = tid; t < 1024; t += 128) sw[t] = wsrc[t];
        __syncthreads();
#pragma unroll
        for (int r = 0; r < 8; r += 4) {
            const __half2* e0 = (const __half2*)(g_E + (size_t)(wrow0 + r + 0) * HW + strip);
            const __half2* e1 = (const __half2*)(g_E + (size_t)(wrow0 + r + 1) * HW + strip);
            const __half2* e2 = (const __half2*)(g_E + (size_t)(wrow0 + r + 2) * HW + strip);
            const __half2* e3 = (const __half2*)(g_E + (size_t)(wrow0 + r + 3) * HW + strip);
#pragma unroll 4
            for (int k = 0; k < 16; ++k) {
                int h = lane + k * 32;
                float2 w0 = sw[2 * h], w1 = sw[2 * h + 1];
                float2 f;
                f = __half22float2(e0[h]);
                accB[r + 0] += f.x * w0.x + f.y * w1.x;
                accG[r + 0] += f.x * w0.y + f.y * w1.y;
                f = __half22float2(e1[h]);
                accB[r + 1] += f.x * w0.x + f.y * w1.x;
                accG[r + 1] += f.x * w0.y + f.y * w1.y;
                f = __half22float2(e2[h]);
                accB[r + 2] += f.x * w0.x + f.y * w1.x;
                accG[r + 2] += f.x * w0.y + f.y * w1.y;
                f = __half22float2(e3[h]);
                accB[r + 3] += f.x * w0.x + f.y * w1.x;
                accG[r + 3] += f.x * w0.y + f.y * w1.y;
            }
        }
    }
#pragma unroll
    for (int r = 0; r < 8; ++r) {
        float b = accB[r], g = accG[r];
#pragma unroll
        for (int o = 16; o > 0; o >>= 1) {
            b += __shfl_down_sync(0xFFFFFFFFu, b, o);
            g += __shfl_down_sync(0xFFFFFFFFu, g, o);
        }
        if (lane == 0) { g_bhat[wrow0 + r] = b; g_ghat[wrow0 + r] = g; }
    }
}

// 7) out[c,p] = gama_hat[p]*feat_src[c,p] + beta_hat[p]
__global__ void finalize_kernel(const float* __restrict__ fs, float* __restrict__ out) {
    int t = blockIdx.x * blockDim.x + threadIdx.x;
    if (t >= NF) return;
    int p = t % HW;
    out[t] = fmaf(g_ghat[p], fs[t], g_bhat[p]);
}

extern "C" void kernel_launch(void* const* d_in, const int* in_sizes, int n_in,
                              void* d_out, int out_size) {
    const float* fs = (const float*)d_in[0];
    const float* fr = (const float*)d_in[1];
    const float* ls = (const float*)d_in[2];
    const float* lr = (const float*)d_in[3];
    const int*   ms = (const int*)d_in[4];
    const int*   mr = (const int*)d_in[5];
    const float* w1 = (const float*)d_in[6];
    const float* b1 = (const float*)d_in[7];
    const float* w2 = (const float*)d_in[8];
    const float* b2 = (const float*)d_in[9];
    float* out = (float*)d_out;

    cudaFuncSetAttribute(gemm_hmma_kernel,
                         cudaFuncAttributeMaxDynamicSharedMemorySize, GEMM_DSMEM);

    prep_src_bf16<<<(HW * KBIG + 255) / 256, 256>>>(fs, ls);
    dim3 trg(HW / 32, KSEG / 32);              // k covers [0,416) incl. landmark + pads
    prep_ref_bf16<<<trg, dim3(32, 8)>>>(fr, lr);
    prep_betagama<<<(HW + 255) / 256, 256>>>(fr, ms, mr, w1, b1, w2, b2);

    dim3 gemm_grid(HW / 128, HW / 128);        // 72 x 72
    gemm_hmma_kernel<<<gemm_grid, 128, GEMM_DSMEM>>>();

    mergestats_kernel<<<HW / 256, 256>>>();
    rowsum_kernel<<<HW / 32, 128>>>();         // 288 CTAs of 32 rows
    finalize_kernel<<<(NF + 255) / 256, 256>>>(fs, out);
}

// round 16
// speedup vs baseline: 1.2802x; 1.2802x over previous
#include <cuda_runtime.h>
#include <cuda_bf16.h>
#include <math_constants.h>
#include <cstdint>

#define HW 9216            // 96*96
#define CK 392             // 256 + 136
#define NF (256 * HW)
#define KSEG 416           // full-K hi segment (13 chunks of 32)
#define KLM 160            // landmark cross segment (136 padded to 160)
#define KBIG 736           // [Ah_full | Ah_lm | Al_lm] x [Bh_full | Bl_lm | Bh_lm]
#define NCHKS 23           // KBIG / 32
#define NBLK 72            // row blocks of 128 (per-CTA colstat partials)
#define ASTG 8192          // A stage bytes: 128 rows x 64B
#define BSTG 8192          // B stage bytes: 128 rows x 64B
#define GEMM_DSMEM (4 * (ASTG + BSTG))   // 64 KB, 4-stage ring -> 2 CTAs/SM

// ===================== static device scratch =====================
__device__ __align__(16) __nv_bfloat16 g_Abig[(size_t)HW * KBIG]; // (9216,736) K-major
__device__ __align__(16) __nv_bfloat16 g_Bbig[(size_t)HW * KBIG]; // transposed (n,k) K-major
__device__ __align__(16) float g_A[(size_t)HW * HW];              // 340 MB logits
__device__ float g_pm[NBLK * HW];
__device__ float g_ps[NBLK * HW];
__device__ float g_beta[HW], g_gama[HW], g_M[HW];
__device__ float g_colmax[HW], g_wb[HW], g_wg[HW];
__device__ float g_bhat[HW], g_ghat[HW];

// ===================== PTX helpers (non-'a' features only) =====================
__device__ __forceinline__ uint32_t smem_u32(const void* p) {
    uint32_t a;
    asm("{ .reg .u64 t; cvta.to.shared.u64 t, %1; cvt.u32.u64 %0, t; }" : "=r"(a) : "l"(p));
    return a;
}
__device__ __forceinline__ void cp16(uint32_t saddr, const void* g) {
    asm volatile("cp.async.cg.shared.global [%0], [%1], 16;" :: "r"(saddr), "l"(g));
}
#define CP_COMMIT() asm volatile("cp.async.commit_group;" ::: "memory")
#define CP_WAIT(n)  asm volatile("cp.async.wait_group %0;" :: "n"(n) : "memory")
#define LDSM_X4(r0, r1, r2, r3, addr) \
    asm volatile("ldmatrix.sync.aligned.m8n8.x4.shared.b16 {%0,%1,%2,%3}, [%4];" \
        : "=r"(r0), "=r"(r1), "=r"(r2), "=r"(r3) : "r"(addr))
#define MMA16816(d, a, b) \
    asm volatile("mma.sync.aligned.m16n8k16.row.col.f32.bf16.bf16.f32 " \
        "{%0,%1,%2,%3}, {%4,%5,%6,%7}, {%8,%9}, {%0,%1,%2,%3};" \
        : "+f"((d)[0]), "+f"((d)[1]), "+f"((d)[2]), "+f"((d)[3]) \
        : "r"((a)[0]), "r"((a)[1]), "r"((a)[2]), "r"((a)[3]), "r"((b)[0]), "r"((b)[1]))

// smem tile layout: [rows][32 bf16] = 64B rows; 16B-chunk swizzle c ^= (r>>1)&3
__device__ __forceinline__ uint32_t swz(int r, int c) {
    return (uint32_t)(r * 64 + ((c ^ ((r >> 1) & 3)) << 4));
}

// 1a) A': seg0 = hi(full k, padded), seg1 = hi(landmark), seg2 = lo(landmark).
__global__ void prep_src_bf16(const float* __restrict__ fs, const float* __restrict__ ls) {
    int t = blockIdx.x * blockDim.x + threadIdx.x;
    if (t >= HW * KBIG) return;
    int m = t / KBIG, kp = t - m * KBIG;
    int k;
    bool lo = false;
    if (kp < KSEG)            k = kp;                       // hi, full K
    else if (kp < KSEG + KLM) k = 256 + (kp - KSEG);        // hi, landmark
    else { k = 256 + (kp - KSEG - KLM); lo = true; }        // lo, landmark
    float x = 0.0f;
    if (k < CK) {
        int s = m * CK + k;
        x = (s < NF) ? 0.01f * fs[s] : ls[s - NF];
    }
    __nv_bfloat16 h = __float2bfloat16(x);
    g_Abig[t] = lo ? __float2bfloat16(x - __bfloat162float(h)) : h;
}

// 1b) B' transposed: seg0 = hi(full), seg1 = lo(landmark), seg2 = hi(landmark).
__global__ void prep_ref_bf16(const float* __restrict__ fr, const float* __restrict__ lr) {
    __shared__ float tile[32][33];
    int k0 = blockIdx.y * 32, n0 = blockIdx.x * 32;
    int tx = threadIdx.x, ty = threadIdx.y;   // (32, 8)
#pragma unroll
    for (int i = 0; i < 32; i += 8) {
        int k = k0 + ty + i, n = n0 + tx;
        float x = 0.0f;
        if (k < CK) x = (k < 256) ? 0.01f * fr[k * HW + n] : lr[(k - 256) * HW + n];
        tile[ty + i][tx] = x;
    }
    __syncthreads();
#pragma unroll
    for (int i = 0; i < 32; i += 8) {
        int n = n0 + ty + i, k = k0 + tx;       // k in [0, 416)
        float x = tile[tx][ty + i];
        __nv_bfloat16 h = __float2bfloat16(x);
        size_t o = (size_t)n * KBIG;
        g_Bbig[o + k] = h;                       // seg0: hi full
        if (k >= 256) {                          // landmark (incl. zero pad k>=392)
            int j = k - 256;                     // [0, 160)
            g_Bbig[o + KSEG + j] = __float2bfloat16(x - __bfloat162float(h));  // seg1: lo
            g_Bbig[o + KSEG + KLM + j] = h;                                    // seg2: hi
        }
    }
}

// 2) 1x1 convs (256->1) + mask equality vector.
__global__ void prep_betagama(const float* __restrict__ fr,
                              const int* __restrict__ ms, const int* __restrict__ mr,
                              const float* __restrict__ w1, const float* __restrict__ b1,
                              const float* __restrict__ w2, const float* __restrict__ b2) {
    int p = blockIdx.x * blockDim.x + threadIdx.x;
    if (p >= HW) return;
    float b = b1[0], g = b2[0];
#pragma unroll 8
    for (int c = 0; c < 256; c++) {
        float v = fr[c * HW + p];
        b = fmaf(v, w1[c], b);
        g = fmaf(v, w2[c], g);
    }
    g_beta[p] = b;
    g_gama[p] = g;
    g_M[p] = (ms[p] == mr[p]) ? 1.0f : 0.0f;
}

// 3) bf16 HMMA GEMM + fused per-CTA column stats.
//    128x128 CTA tile, 128 threads: 4 warps of 64x64 (2m x 2n), BK=32,
//    4-stage cp.async ring (64 KB -> 2 CTAs/SM), one barrier per chunk.
//    K-loop PHASE-STAGGERED per wave: co-resident CTAs (bid, bid+148) start
//    half a period apart so their per-chunk barriers anti-align and each
//    CTA's MMA stream covers the other's barrier/wait window.
__global__ void __launch_bounds__(128, 2) gemm_hmma_kernel() {
    extern __shared__ __align__(128) char smem_raw[];
    const uint32_t sAu = smem_u32(smem_raw);            // 4 stages x 8192 B
    const uint32_t sBu = sAu + 4 * ASTG;                // 4 stages x 8192 B
    const int tid = threadIdx.x;
    const int wid = tid >> 5, lane = tid & 31;
    const size_t m0 = (size_t)blockIdx.y * 128;
    const size_t n0 = (size_t)blockIdx.x * 128;
    const int mw = (wid & 1) * 64;   // warp m offset in tile
    const int nw = (wid >> 1) * 64;  // warp n offset in tile

    // wave-parity phase: alternate waves of 148 start 11 chunks apart
    const int lbid = blockIdx.y * gridDim.x + blockIdx.x;
    const int phase = ((lbid / 148) & 1) * (NCHKS / 2);

    // per-thread load slots: each stage = 512 16B-chunks -> 4 per thread (A and B)
    const int lc0 = tid & 3;
    uint32_t saS[4];
    const __nv_bfloat16 *gA[4], *gB[4];
#pragma unroll
    for (int j = 0; j < 4; ++j) {
        int r = (tid + j * 128) >> 2;
        saS[j] = swz(r, lc0);
        gA[j] = g_Abig + (m0 + r) * KBIG + lc0 * 8;
        gB[j] = g_Bbig + (n0 + r) * KBIG + lc0 * 8;
    }

    float acc[4][8][4];
#pragma unroll
    for (int i = 0; i < 4; i++)
#pragma unroll
        for (int j = 0; j < 8; j++)
#pragma unroll
            for (int q = 0; q < 4; q++) acc[i][j][q] = 0.0f;

    // ldmatrix lane address components (swizzled)
    const int a_r = (lane & 7) + ((lane >> 3) & 1) * 8;
    const int a_c = lane >> 4;
    const int b_r = (lane & 7) + (lane >> 4) * 8;
    const int b_c = (lane >> 3) & 1;

    // prologue: prefetch schedule-chunks 0..2 (data chunks rotated by phase)
#pragma unroll
    for (int p = 0; p < 3; ++p) {
        int cc = p + phase; if (cc >= NCHKS) cc -= NCHKS;
        const uint32_t oa = (uint32_t)p * ASTG, ob = (uint32_t)p * BSTG;
        const size_t kofs = (size_t)cc * 32;
#pragma unroll
        for (int j = 0; j < 4; ++j) {
            cp16(sAu + oa + saS[j], gA[j] + kofs);
            cp16(sBu + ob + saS[j], gB[j] + kofs);
        }
        CP_COMMIT();
    }

    for (int ch = 0; ch < NCHKS; ++ch) {
        if (ch < NCHKS - 2)      { CP_WAIT(2); }
        else if (ch == NCHKS - 2){ CP_WAIT(1); }
        else                     { CP_WAIT(0); }
        __syncthreads();
        if (ch + 3 < NCHKS) {    // refill ring slot (ch+3)&3 == (ch-1)&3 (free after barrier)
            int cc = ch + 3 + phase; if (cc >= NCHKS) cc -= NCHKS;
            const uint32_t oa = (uint32_t)((ch + 3) & 3) * ASTG;
            const uint32_t ob = (uint32_t)((ch + 3) & 3) * BSTG;
            const size_t kofs = (size_t)cc * 32;
#pragma unroll
            for (int j = 0; j < 4; ++j) {
                cp16(sAu + oa + saS[j], gA[j] + kofs);
                cp16(sBu + ob + saS[j], gB[j] + kofs);
            }
            CP_COMMIT();
        }

        const uint32_t ab = sAu + (uint32_t)(ch & 3) * ASTG;
        const uint32_t bb = sBu + (uint32_t)(ch & 3) * BSTG;
#pragma unroll
        for (int ks = 0; ks < 2; ++ks) {
            uint32_t afr[4][4], bfr[8][2];
#pragma unroll
            for (int mt = 0; mt < 4; ++mt) {
                int r = mw + mt * 16 + a_r;
                LDSM_X4(afr[mt][0], afr[mt][1], afr[mt][2], afr[mt][3],
                        ab + swz(r, 2 * ks + a_c));
            }
#pragma unroll
            for (int np = 0; np < 4; ++np) {
                int r = nw + np * 16 + b_r;
                LDSM_X4(bfr[np * 2][0], bfr[np * 2][1], bfr[np * 2 + 1][0], bfr[np * 2 + 1][1],
                        bb + swz(r, 2 * ks + b_c));
            }
#pragma unroll
            for (int mt = 0; mt < 4; ++mt)
#pragma unroll
                for (int nt = 0; nt < 8; ++nt)
                    MMA16816(acc[mt][nt], afr[mt], bfr[nt]);
        }
    }

    // ---- store fp32 logits (lane: c0c1 at (m=lane/4, n=2*(lane%4)), c2c3 at m+8) ----
    const size_t mbase = m0 + mw + (lane >> 2);
    const size_t nbase = n0 + nw + 2 * (lane & 3);
#pragma unroll
    for (int mt = 0; mt < 4; ++mt) {
#pragma unroll
        for (int nt = 0; nt < 8; ++nt) {
            size_t m = mbase + mt * 16;
            size_t n = nbase + nt * 8;
            *(float2*)&g_A[m * HW + n]       = make_float2(acc[mt][nt][0], acc[mt][nt][1]);
            *(float2*)&g_A[(m + 8) * HW + n] = make_float2(acc[mt][nt][2], acc[mt][nt][3]);
        }
    }

    // ---- fused per-CTA column stats over this 128-row block ----
    // Column identity depends only on (nt, lane&3, p); xor-shuffles 4/8/16 reduce
    // over the 8 lane-groups (rows) preserving lane&3.
    __syncthreads();                       // ring dead; overlay stats scratch
    float* pm_s = (float*)smem_raw;        // [4][64]
    float* ps_s = pm_s + 256;              // [4][64]
#pragma unroll
    for (int nt = 0; nt < 8; ++nt) {
#pragma unroll
        for (int p = 0; p < 2; ++p) {
            float mx = -CUDART_INF_F;
#pragma unroll
            for (int mt = 0; mt < 4; ++mt)
                mx = fmaxf(mx, fmaxf(acc[mt][nt][p], acc[mt][nt][p + 2]));
#pragma unroll
            for (int o = 4; o < 32; o <<= 1)
                mx = fmaxf(mx, __shfl_xor_sync(0xFFFFFFFFu, mx, o));
            float se = 0.0f;
#pragma unroll
            for (int mt = 0; mt < 4; ++mt)
                se += __expf(acc[mt][nt][p] - mx) + __expf(acc[mt][nt][p + 2] - mx);
#pragma unroll
            for (int o = 4; o < 32; o <<= 1)
                se += __shfl_xor_sync(0xFFFFFFFFu, se, o);
            if (lane < 4) {
                int cl = nt * 8 + 2 * lane + p;   // column within warp's 64
                pm_s[wid * 64 + cl] = mx;
                ps_s[wid * 64 + cl] = se;
            }
        }
    }
    __syncthreads();
    // combine 2 m-warps per n-half: tid -> (n-half g = tid>>6, col c = tid&63)
    {
        int g = tid >> 6, c = tid & 63;
        float m = fmaxf(pm_s[(g * 2 + 0) * 64 + c], pm_s[(g * 2 + 1) * 64 + c]);
        float s = ps_s[(g * 2 + 0) * 64 + c] * __expf(pm_s[(g * 2 + 0) * 64 + c] - m)
                + ps_s[(g * 2 + 1) * 64 + c] * __expf(pm_s[(g * 2 + 1) * 64 + c] - m);
        size_t gc = n0 + g * 64 + c;
        g_pm[blockIdx.y * HW + gc] = m;
        g_ps[blockIdx.y * HW + gc] = s;
    }
}

// 5) Merge per-row-block partials; fold mask/beta/gama/colsum into weights.
__global__ void mergestats_kernel() {
    int j = blockIdx.x * blockDim.x + threadIdx.x;
    float m = -CUDART_INF_F;
    for (int c = 0; c < NBLK; c++) m = fmaxf(m, g_pm[c * HW + j]);
    float s = 0.0f;
    for (int c = 0; c < NBLK; c++) s += g_ps[c * HW + j] * __expf(g_pm[c * HW + j] - m);
    g_colmax[j] = m;
    float inv = g_M[j] / s;
    g_wb[j] = g_beta[j] * inv;
    g_wg[j] = g_gama[j] * inv;
}

// 6) One warp per row: beta_hat[i] = sum_j exp(A[i,j]-colmax[j]) * wb[j], same for gama.
__global__ void rowsum_kernel() {
    int warp = (blockIdx.x * blockDim.x + threadIdx.x) >> 5;
    int lane = threadIdx.x & 31;
    const float* row = g_A + (size_t)warp * HW;
    float b = 0.0f, g = 0.0f;
    for (int j0 = lane * 4; j0 < HW; j0 += 128) {
        float4 v  = *(const float4*)(row + j0);
        float4 cm = *(const float4*)(g_colmax + j0);
        float4 wb = *(const float4*)(g_wb + j0);
        float4 wg = *(const float4*)(g_wg + j0);
        float e;
        e = __expf(v.x - cm.x); b = fmaf(e, wb.x, b); g = fmaf(e, wg.x, g);
        e = __expf(v.y - cm.y); b = fmaf(e, wb.y, b); g = fmaf(e, wg.y, g);
        e = __expf(v.z - cm.z); b = fmaf(e, wb.z, b); g = fmaf(e, wg.z, g);
        e = __expf(v.w - cm.w); b = fmaf(e, wb.w, b); g = fmaf(e, wg.w, g);
    }
#pragma unroll
    for (int o = 16; o > 0; o >>= 1) {
        b += __shfl_down_sync(0xFFFFFFFFu, b, o);
        g += __shfl_down_sync(0xFFFFFFFFu, g, o);
    }
    if (lane == 0) { g_bhat[warp] = b; g_ghat[warp] = g; }
}

// 7) out[c,p] = gama_hat[p]*feat_src[c,p] + beta_hat[p]
__global__ void finalize_kernel(const float* __restrict__ fs, float* __restrict__ out) {
    int t = blockIdx.x * blockDim.x + threadIdx.x;
    if (t >= NF) return;
    int p = t % HW;
    out[t] = fmaf(g_ghat[p], fs[t], g_bhat[p]);
}

extern "C" void kernel_launch(void* const* d_in, const int* in_sizes, int n_in,
                              void* d_out, int out_size) {
    const float* fs = (const float*)d_in[0];
    const float* fr = (const float*)d_in[1];
    const float* ls = (const float*)d_in[2];
    const float* lr = (const float*)d_in[3];
    const int*   ms = (const int*)d_in[4];
    const int*   mr = (const int*)d_in[5];
    const float* w1 = (const float*)d_in[6];
    const float* b1 = (const float*)d_in[7];
    const float* w2 = (const float*)d_in[8];
    const float* b2 = (const float*)d_in[9];
    float* out = (float*)d_out;

    cudaFuncSetAttribute(gemm_hmma_kernel,
                         cudaFuncAttributeMaxDynamicSharedMemorySize, GEMM_DSMEM);

    prep_src_bf16<<<(HW * KBIG + 255) / 256, 256>>>(fs, ls);
    dim3 trg(HW / 32, KSEG / 32);              // k covers [0,416) incl. landmark + pads
    prep_ref_bf16<<<trg, dim3(32, 8)>>>(fr, lr);
    prep_betagama<<<(HW + 255) / 256, 256>>>(fr, ms, mr, w1, b1, w2, b2);

    dim3 gemm_grid(HW / 128, HW / 128);        // 72 x 72
    gemm_hmma_kernel<<<gemm_grid, 128, GEMM_DSMEM>>>();

    mergestats_kernel<<<HW / 256, 256>>>();
    rowsum_kernel<<<(HW * 32) / 256, 256>>>();
    finalize_kernel<<<(NF + 255) / 256, 256>>>(fs, out);
}

// round 17
// speedup vs baseline: 1.3437x; 1.0495x over previous
#include <cuda_runtime.h>
#include <cuda_bf16.h>
#include <cuda_fp16.h>
#include <math_constants.h>
#include <cstdint>

#define HW 9216            // 96*96
#define CK 392             // 256 + 136
#define NF (256 * HW)
#define KSEG 416           // full-K hi segment (13 chunks of 32)
#define KLM 160            // landmark cross segment (136 padded to 160)
#define KBIG 736           // [Ah_full | Ah_lm | Al_lm] x [Bh_full | Bl_lm | Bh_lm]
#define NCHKS 23           // KBIG / 32
#define NBLK 144           // row blocks of 64 (per-warp colstat partials)
#define STRIP 2304         // HW / 4 rowsum column strip
#define ASTG 8192          // A stage bytes: 128 rows x 64B
#define BSTG 8192          // B stage bytes: 128 rows x 64B
#define GEMM_DSMEM (4 * (ASTG + BSTG))   // 64 KB, 4-stage ring -> 2 CTAs/SM

// ===================== static device scratch =====================
__device__ __align__(16) __nv_bfloat16 g_Abig[(size_t)HW * KBIG]; // (9216,736) K-major
__device__ __align__(16) __nv_bfloat16 g_Bbig[(size_t)HW * KBIG]; // transposed (n,k) K-major
__device__ __align__(16) __half g_E[(size_t)HW * HW];             // 170 MB exp(A - blkmax)
__device__ float g_pm[(size_t)NBLK * HW];
__device__ float g_ps[(size_t)NBLK * HW];
__device__ __align__(16) float2 g_wcomb[(size_t)NBLK * HW];       // (wb,wg)*corr per (blk,col)
__device__ float g_pb[4 * HW], g_pg[4 * HW];                      // betagama partials
__device__ float g_colmax[HW], g_wb[HW], g_wg[HW];
__device__ float g_bhat[HW], g_ghat[HW];

// ===================== PTX helpers (non-'a' features only) =====================
__device__ __forceinline__ uint32_t smem_u32(const void* p) {
    uint32_t a;
    asm("{ .reg .u64 t; cvta.to.shared.u64 t, %1; cvt.u32.u64 %0, t; }" : "=r"(a) : "l"(p));
    return a;
}
__device__ __forceinline__ void cp16(uint32_t saddr, const void* g) {
    asm volatile("cp.async.cg.shared.global [%0], [%1], 16;" :: "r"(saddr), "l"(g));
}
#define CP_COMMIT() asm volatile("cp.async.commit_group;" ::: "memory")
#define CP_WAIT(n)  asm volatile("cp.async.wait_group %0;" :: "n"(n) : "memory")
#define LDSM_X4(r0, r1, r2, r3, addr) \
    asm volatile("ldmatrix.sync.aligned.m8n8.x4.shared.b16 {%0,%1,%2,%3}, [%4];" \
        : "=r"(r0), "=r"(r1), "=r"(r2), "=r"(r3) : "r"(addr))
#define MMA16816(d, a, b) \
    asm volatile("mma.sync.aligned.m16n8k16.row.col.f32.bf16.bf16.f32 " \
        "{%0,%1,%2,%3}, {%4,%5,%6,%7}, {%8,%9}, {%0,%1,%2,%3};" \
        : "+f"((d)[0]), "+f"((d)[1]), "+f"((d)[2]), "+f"((d)[3]) \
        : "r"((a)[0]), "r"((a)[1]), "r"((a)[2]), "r"((a)[3]), "r"((b)[0]), "r"((b)[1]))

// smem tile layout: [rows][32 bf16] = 64B rows; 16B-chunk swizzle c ^= (r>>1)&3
__device__ __forceinline__ uint32_t swz(int r, int c) {
    return (uint32_t)(r * 64 + ((c ^ ((r >> 1) & 3)) << 4));
}

// 1a) A': seg0 = hi(full k, padded), seg1 = hi(landmark), seg2 = lo(landmark).
__global__ void prep_src_bf16(const float* __restrict__ fs, const float* __restrict__ ls) {
    int t = blockIdx.x * blockDim.x + threadIdx.x;
    if (t >= HW * KBIG) return;
    int m = t / KBIG, kp = t - m * KBIG;
    int k;
    bool lo = false;
    if (kp < KSEG)            k = kp;                       // hi, full K
    else if (kp < KSEG + KLM) k = 256 + (kp - KSEG);        // hi, landmark
    else { k = 256 + (kp - KSEG - KLM); lo = true; }        // lo, landmark
    float x = 0.0f;
    if (k < CK) {
        int s = m * CK + k;
        x = (s < NF) ? 0.01f * fs[s] : ls[s - NF];
    }
    __nv_bfloat16 h = __float2bfloat16(x);
    g_Abig[t] = lo ? __float2bfloat16(x - __bfloat162float(h)) : h;
}

// 1b) B' transposed: seg0 = hi(full), seg1 = lo(landmark), seg2 = hi(landmark).
__global__ void prep_ref_bf16(const float* __restrict__ fr, const float* __restrict__ lr) {
    __shared__ float tile[32][33];
    int k0 = blockIdx.y * 32, n0 = blockIdx.x * 32;
    int tx = threadIdx.x, ty = threadIdx.y;   // (32, 8)
#pragma unroll
    for (int i = 0; i < 32; i += 8) {
        int k = k0 + ty + i, n = n0 + tx;
        float x = 0.0f;
        if (k < CK) x = (k < 256) ? 0.01f * fr[k * HW + n] : lr[(k - 256) * HW + n];
        tile[ty + i][tx] = x;
    }
    __syncthreads();
#pragma unroll
    for (int i = 0; i < 32; i += 8) {
        int n = n0 + ty + i, k = k0 + tx;       // k in [0, 416)
        float x = tile[tx][ty + i];
        __nv_bfloat16 h = __float2bfloat16(x);
        size_t o = (size_t)n * KBIG;
        g_Bbig[o + k] = h;                       // seg0: hi full
        if (k >= 256) {                          // landmark (incl. zero pad k>=392)
            int j = k - 256;                     // [0, 160)
            g_Bbig[o + KSEG + j] = __float2bfloat16(x - __bfloat162float(h));  // seg1: lo
            g_Bbig[o + KSEG + KLM + j] = h;                                    // seg2: hi
        }
    }
}

// 2) 1x1 conv partials: blockIdx.y selects 64-channel group (4 groups).
__global__ void prep_betagama(const float* __restrict__ fr,
                              const float* __restrict__ w1, const float* __restrict__ w2) {
    int p = blockIdx.x * blockDim.x + threadIdx.x;
    int yg = blockIdx.y;
    float b = 0.0f, g = 0.0f;
#pragma unroll 8
    for (int c = yg * 64; c < yg * 64 + 64; c++) {
        float v = fr[c * HW + p];
        b = fmaf(v, w1[c], b);
        g = fmaf(v, w2[c], g);
    }
    g_pb[yg * HW + p] = b;
    g_pg[yg * HW + p] = g;
}

// 3) bf16 HMMA GEMM; epilogue stores e = fp16(exp(acc - per-64-row colmax)) and
//    per-(64-row warp block, column) (max, sumexp). 128x128 CTA tile, 128 threads
//    (4 warps of 64x64), BK=32, 4-stage cp.async ring, 2 CTAs/SM.
__global__ void __launch_bounds__(128, 2) gemm_hmma_kernel() {
    extern __shared__ __align__(128) char smem_raw[];
    const uint32_t sAu = smem_u32(smem_raw);            // 4 stages x 8192 B
    const uint32_t sBu = sAu + 4 * ASTG;                // 4 stages x 8192 B
    const int tid = threadIdx.x;
    const int wid = tid >> 5, lane = tid & 31;
    const size_t m0 = (size_t)blockIdx.y * 128;
    const size_t n0 = (size_t)blockIdx.x * 128;
    const int mw = (wid & 1) * 64;   // warp m offset in tile
    const int nw = (wid >> 1) * 64;  // warp n offset in tile

    const int lc0 = tid & 3;
    uint32_t saS[4];
    const __nv_bfloat16 *gA[4], *gB[4];
#pragma unroll
    for (int j = 0; j < 4; ++j) {
        int r = (tid + j * 128) >> 2;
        saS[j] = swz(r, lc0);
        gA[j] = g_Abig + (m0 + r) * KBIG + lc0 * 8;
        gB[j] = g_Bbig + (n0 + r) * KBIG + lc0 * 8;
    }

    float acc[4][8][4];
#pragma unroll
    for (int i = 0; i < 4; i++)
#pragma unroll
        for (int j = 0; j < 8; j++)
#pragma unroll
            for (int q = 0; q < 4; q++) acc[i][j][q] = 0.0f;

    const int a_r = (lane & 7) + ((lane >> 3) & 1) * 8;
    const int a_c = lane >> 4;
    const int b_r = (lane & 7) + (lane >> 4) * 8;
    const int b_c = (lane >> 3) & 1;

#pragma unroll
    for (int p = 0; p < 3; ++p) {
        const uint32_t oa = (uint32_t)p * ASTG, ob = (uint32_t)p * BSTG;
        const size_t kofs = (size_t)p * 32;
#pragma unroll
        for (int j = 0; j < 4; ++j) {
            cp16(sAu + oa + saS[j], gA[j] + kofs);
            cp16(sBu + ob + saS[j], gB[j] + kofs);
        }
        CP_COMMIT();
    }

    for (int ch = 0; ch < NCHKS; ++ch) {
        if (ch < NCHKS - 2)      { CP_WAIT(2); }
        else if (ch == NCHKS - 2){ CP_WAIT(1); }
        else                     { CP_WAIT(0); }
        __syncthreads();
        if (ch + 3 < NCHKS) {
            const uint32_t oa = (uint32_t)((ch + 3) & 3) * ASTG;
            const uint32_t ob = (uint32_t)((ch + 3) & 3) * BSTG;
            const size_t kofs = (size_t)(ch + 3) * 32;
#pragma unroll
            for (int j = 0; j < 4; ++j) {
                cp16(sAu + oa + saS[j], gA[j] + kofs);
                cp16(sBu + ob + saS[j], gB[j] + kofs);
            }
            CP_COMMIT();
        }

        const uint32_t ab = sAu + (uint32_t)(ch & 3) * ASTG;
        const uint32_t bb = sBu + (uint32_t)(ch & 3) * BSTG;
#pragma unroll
        for (int ks = 0; ks < 2; ++ks) {
            uint32_t afr[4][4], bfr[8][2];
#pragma unroll
            for (int mt = 0; mt < 4; ++mt) {
                int r = mw + mt * 16 + a_r;
                LDSM_X4(afr[mt][0], afr[mt][1], afr[mt][2], afr[mt][3],
                        ab + swz(r, 2 * ks + a_c));
            }
#pragma unroll
            for (int np = 0; np < 4; ++np) {
                int r = nw + np * 16 + b_r;
                LDSM_X4(bfr[np * 2][0], bfr[np * 2][1], bfr[np * 2 + 1][0], bfr[np * 2 + 1][1],
                        bb + swz(r, 2 * ks + b_c));
            }
#pragma unroll
            for (int mt = 0; mt < 4; ++mt)
#pragma unroll
                for (int nt = 0; nt < 8; ++nt)
                    MMA16816(acc[mt][nt], afr[mt], bfr[nt]);
        }
    }

    // ---- epilogue: per-warp (64-row) column stats + fp16 e store ----
    const size_t mbase = m0 + mw + (lane >> 2);
    const size_t nbase = n0 + nw + 2 * (lane & 3);
    const size_t blkrow = (size_t)blockIdx.y * 2 + (wid & 1);
#pragma unroll
    for (int nt = 0; nt < 8; ++nt) {
        float ev[4][4];
#pragma unroll
        for (int p = 0; p < 2; ++p) {
            float mx = -CUDART_INF_F;
#pragma unroll
            for (int mt = 0; mt < 4; ++mt)
                mx = fmaxf(mx, fmaxf(acc[mt][nt][p], acc[mt][nt][p + 2]));
#pragma unroll
            for (int o = 4; o < 32; o <<= 1)
                mx = fmaxf(mx, __shfl_xor_sync(0xFFFFFFFFu, mx, o));
            float se = 0.0f;
#pragma unroll
            for (int mt = 0; mt < 4; ++mt) {
                ev[mt][p]     = __expf(acc[mt][nt][p]     - mx);
                ev[mt][p + 2] = __expf(acc[mt][nt][p + 2] - mx);
                se += ev[mt][p] + ev[mt][p + 2];
            }
#pragma unroll
            for (int o = 4; o < 32; o <<= 1)
                se += __shfl_xor_sync(0xFFFFFFFFu, se, o);
            if (lane < 4) {
                size_t col = n0 + (size_t)(wid >> 1) * 64 + nt * 8 + 2 * lane + p;
                g_pm[blkrow * HW + col] = mx;
                g_ps[blkrow * HW + col] = se;
            }
        }
#pragma unroll
        for (int mt = 0; mt < 4; ++mt) {
            size_t r = mbase + mt * 16, c = nbase + nt * 8;
            *(__half2*)&g_E[r * HW + c]       = __floats2half2_rn(ev[mt][0], ev[mt][1]);
            *(__half2*)&g_E[(r + 8) * HW + c] = __floats2half2_rn(ev[mt][2], ev[mt][3]);
        }
    }
}

// 4) merge: ONE WARP PER COLUMN j. Reduce 144 block partials (max, sumexp),
//    fold beta/gama partials + bias + mask, zero bhat/ghat.
__global__ void __launch_bounds__(256) merge_kernel(const int* __restrict__ ms,
                                                    const int* __restrict__ mr,
                                                    const float* __restrict__ b1,
                                                    const float* __restrict__ b2) {
    int j = (blockIdx.x * blockDim.x + threadIdx.x) >> 5;
    int lane = threadIdx.x & 31;
    float m = -CUDART_INF_F;
#pragma unroll
    for (int c = lane; c < NBLK; c += 32)
        m = fmaxf(m, g_pm[(size_t)c * HW + j]);
#pragma unroll
    for (int o = 16; o > 0; o >>= 1)
        m = fmaxf(m, __shfl_xor_sync(0xFFFFFFFFu, m, o));
    float s = 0.0f;
#pragma unroll
    for (int c = lane; c < NBLK; c += 32)
        s += g_ps[(size_t)c * HW + j] * __expf(g_pm[(size_t)c * HW + j] - m);
    float b = (lane < 4) ? g_pb[lane * HW + j] : 0.0f;
    float g = (lane < 4) ? g_pg[lane * HW + j] : 0.0f;
#pragma unroll
    for (int o = 16; o > 0; o >>= 1) {
        s += __shfl_xor_sync(0xFFFFFFFFu, s, o);
        b += __shfl_xor_sync(0xFFFFFFFFu, b, o);
        g += __shfl_xor_sync(0xFFFFFFFFu, g, o);
    }
    if (lane == 0) {
        float M = (ms[j] == mr[j]) ? 1.0f : 0.0f;
        float inv = M / s;
        g_colmax[j] = m;
        g_wb[j] = (b + b1[0]) * inv;
        g_wg[j] = (g + b2[0]) * inv;
        g_bhat[j] = 0.0f;
        g_ghat[j] = 0.0f;
    }
}

// 5) wcomb table: fully parallel over (blk, col).
__global__ void wcomb_kernel() {
    int j = blockIdx.x * blockDim.x + threadIdx.x;
    int c = blockIdx.y;
    float corr = __expf(g_pm[(size_t)c * HW + j] - g_colmax[j]);
    g_wcomb[(size_t)c * HW + j] = make_float2(corr * g_wb[j], corr * g_wg[j]);
}

// 6) rowsum: grid (4 strips, 144 blocks of 64 rows), 256 threads.
//    Stage wcomb strip (18 KB) in smem; warp handles 8 rows; 36 independent
//    half2 loads per row per lane; atomicAdd strip partials.
__global__ void __launch_bounds__(256) rowsum_kernel() {
    __shared__ __align__(16) float2 sw[STRIP];
    const int tid = threadIdx.x, wid = tid >> 5, lane = tid & 31;
    const int col0 = blockIdx.x * STRIP;
    const int blk = blockIdx.y;
    const float2* wsrc = g_wcomb + (size_t)blk * HW + col0;
    for (int t = tid; t < STRIP; t += 256) sw[t] = wsrc[t];
    __syncthreads();
    const int row0 = blk * 64 + wid * 8;
#pragma unroll 1
    for (int r = 0; r < 8; ++r) {
        const __half2* e = (const __half2*)(g_E + (size_t)(row0 + r) * HW + col0);
        float b = 0.0f, g = 0.0f;
#pragma unroll
        for (int k = 0; k < STRIP / 64; ++k) {       // 36
            int h = lane + k * 32;
            float2 f = __half22float2(e[h]);
            float2 w0 = sw[2 * h], w1 = sw[2 * h + 1];
            b += f.x * w0.x + f.y * w1.x;
            g += f.x * w0.y + f.y * w1.y;
        }
#pragma unroll
        for (int o = 16; o > 0; o >>= 1) {
            b += __shfl_down_sync(0xFFFFFFFFu, b, o);
            g += __shfl_down_sync(0xFFFFFFFFu, g, o);
        }
        if (lane == 0) {
            atomicAdd(&g_bhat[row0 + r], b);
            atomicAdd(&g_ghat[row0 + r], g);
        }
    }
}

// 7) out[c,p] = gama_hat[p]*feat_src[c,p] + beta_hat[p]
__global__ void finalize_kernel(const float* __restrict__ fs, float* __restrict__ out) {
    int t = blockIdx.x * blockDim.x + threadIdx.x;
    if (t >= NF) return;
    int p = t % HW;
    out[t] = fmaf(g_ghat[p], fs[t], g_bhat[p]);
}

extern "C" void kernel_launch(void* const* d_in, const int* in_sizes, int n_in,
                              void* d_out, int out_size) {
    const float* fs = (const float*)d_in[0];
    const float* fr = (const float*)d_in[1];
    const float* ls = (const float*)d_in[2];
    const float* lr = (const float*)d_in[3];
    const int*   ms = (const int*)d_in[4];
    const int*   mr = (const int*)d_in[5];
    const float* w1 = (const float*)d_in[6];
    const float* b1 = (const float*)d_in[7];
    const float* w2 = (const float*)d_in[8];
    const float* b2 = (const float*)d_in[9];
    float* out = (float*)d_out;

    cudaFuncSetAttribute(gemm_hmma_kernel,
                         cudaFuncAttributeMaxDynamicSharedMemorySize, GEMM_DSMEM);

    prep_src_bf16<<<(HW * KBIG + 255) / 256, 256>>>(fs, ls);
    dim3 trg(HW / 32, KSEG / 32);
    prep_ref_bf16<<<trg, dim3(32, 8)>>>(fr, lr);
    prep_betagama<<<dim3(HW / 256, 4), 256>>>(fr, w1, w2);

    dim3 gemm_grid(HW / 128, HW / 128);        // 72 x 72
    gemm_hmma_kernel<<<gemm_grid, 128, GEMM_DSMEM>>>();

    merge_kernel<<<(HW * 32) / 256, 256>>>(ms, mr, b1, b2);   // warp per column
    wcomb_kernel<<<dim3(HW / 256, NBLK), 256>>>();
    rowsum_kernel<<<dim3(4, NBLK), 256>>>();
    finalize_kernel<<<(NF + 255) / 256, 256>>>(fs, out);
}